// round 1
// baseline (speedup 1.0000x reference)
#include <cuda_runtime.h>
#include <cstdint>
#include <math.h>

#define BATCH 8
#define CIN   28
#define COUT  28
#define HH    256
#define WW    256
#define DGRP  7
#define KHT   7
#define CPG   4

typedef unsigned long long ull;

// ---- packed f32x2 helpers (Blackwell sm_103a) ----
__device__ __forceinline__ ull pk2(float a, float b) {
    ull r; asm("mov.b64 %0, {%1,%2};" : "=l"(r) : "f"(a), "f"(b)); return r;
}
__device__ __forceinline__ ull pk1(float a) { return pk2(a, a); }
__device__ __forceinline__ void upk(ull v, float& a, float& b) {
    asm("mov.b64 {%0,%1}, %2;" : "=f"(a), "=f"(b) : "l"(v));
}
__device__ __forceinline__ ull f2fma(ull a, ull b, ull c) {
    ull d; asm("fma.rn.f32x2 %0, %1, %2, %3;" : "=l"(d) : "l"(a), "l"(b), "l"(c)); return d;
}
__device__ __forceinline__ ull f2mul(ull a, ull b) {
    ull d; asm("mul.rn.f32x2 %0, %1, %2;" : "=l"(d) : "l"(a), "l"(b)); return d;
}
__device__ __forceinline__ void cp16(void* dst, const void* src) {
    unsigned s = (unsigned)__cvta_generic_to_shared(dst);
    asm volatile("cp.async.cg.shared.global [%0], [%1], 16;" :: "r"(s), "l"(src));
}

// ---- precomputed weights (stage-3 folded into stage-2) ----
__device__ float g_W1T[DGRP * KHT * CPG * COUT];  // [g][i][c][o]
__device__ float g_W2T[COUT * 7 * COUT];          // [o2][kw][oc]
__device__ float g_b2[COUT];

__global__ void prep_kernel(const float* __restrict__ weight, const float* __restrict__ w_t,
                            const float* __restrict__ b_t, const float* __restrict__ w_m,
                            const float* __restrict__ b_m) {
    int t = threadIdx.x;
    for (int idx = t; idx < DGRP * KHT * CPG * COUT; idx += blockDim.x) {
        int o = idx % COUT;
        int c = (idx / COUT) % CPG;
        int i = (idx / (COUT * CPG)) % KHT;
        int g = idx / (COUT * CPG * KHT);
        g_W1T[idx] = weight[(o * CIN + (g * CPG + c)) * KHT + i];
    }
    for (int idx = t; idx < COUT * 7 * COUT; idx += blockDim.x) {
        int oc = idx % COUT;
        int kw = (idx / COUT) % 7;
        int o2 = idx / (COUT * 7);
        int f = oc >> 2, cc = oc & 3;
        float s = 0.f;
#pragma unroll
        for (int g = 0; g < DGRP; g++)
            s += w_m[f * DGRP + g] * w_t[((g * CPG + cc) * COUT + o2) * 7 + kw];
        g_W2T[idx] = s;
    }
    if (t < COUT) {
        int f = t >> 2, cc = t & 3;
        float s = 0.f;
#pragma unroll
        for (int g = 0; g < DGRP; g++) s += w_m[f * DGRP + g] * b_t[g * CPG + cc];
        g_b2[t] = s + b_m[f];
    }
}

// ---- shared memory layout (bytes) ----
constexpr int SM_Y0  = 0;                      // int[49]
constexpr int SM_Y1  = 256;                    // int[49]
constexpr int SM_TW0 = 512;                    // float[49]
constexpr int SM_TW1 = 768;                    // float[49]
constexpr int SM_W1  = 1024;                   // float[5488]
constexpr int SM_W2  = SM_W1 + 21952;          // float[5488]
constexpr int SM_B1  = SM_W2 + 21952;          // float[28]
constexpr int SM_B2  = SM_B1 + 128;            // float[28]
constexpr int SM_XB  = SM_B2 + 128;            // float[2*14*4*256]
constexpr int SM_R   = SM_XB + 2 * 14336 * 4;  // float[28*264]
constexpr int SM_RS  = SM_R + 28 * 264 * 4;    // float[28*264], shifted copy
constexpr int SMEM_BYTES = SM_RS + 28 * 264 * 4;  // 219008

__global__ void __launch_bounds__(224, 1)
harmonic_kernel(const float* __restrict__ x, const float* __restrict__ bias1,
                float* __restrict__ out) {
    extern __shared__ char smraw[];
    int*   y0c = (int*)(smraw + SM_Y0);
    int*   y1c = (int*)(smraw + SM_Y1);
    float* tw0 = (float*)(smraw + SM_TW0);
    float* tw1 = (float*)(smraw + SM_TW1);
    float* W1s = (float*)(smraw + SM_W1);
    float* W2s = (float*)(smraw + SM_W2);
    float* b1s = (float*)(smraw + SM_B1);
    float* b2s = (float*)(smraw + SM_B2);
    float* xbf = (float*)(smraw + SM_XB);
    float* R   = (float*)(smraw + SM_R);
    float* Rs  = (float*)(smraw + SM_RS);

    const int tid = threadIdx.x;
    const int h = blockIdx.x;
    const int b = blockIdx.y;

    // weights -> smem
    for (int idx = tid; idx < 5488; idx += 224) W1s[idx] = g_W1T[idx];
    for (int idx = tid; idx < 5488; idx += 224) W2s[idx] = g_W2T[idx];
    if (tid < 28) { b1s[tid] = bias1[tid]; b2s[tid] = g_b2[tid]; }

    // sampling taps for this row h:  yp = (h+1)(i+1)/(g+1) - 4
    if (tid < 49) {
        int g = tid / 7, i = tid % 7;
        double yp = (double)((h + 1) * (i + 1)) / (double)(g + 1) - 4.0;
        double y0 = floor(yp);
        float fy = (float)(yp - y0);
        int y0i = (int)y0;
        bool v0 = (y0i >= 0) && (y0i <= HH - 1);
        bool v1 = (y0i + 1 >= 0) && (y0i + 1 <= HH - 1);
        int ya = y0i < 0 ? 0 : (y0i > HH - 1 ? HH - 1 : y0i);
        int yb = (y0i + 1) < 0 ? 0 : (y0i + 1 > HH - 1 ? HH - 1 : y0i + 1);
        y0c[tid] = ya; y1c[tid] = yb;
        tw0[tid] = v0 ? (1.0f - fy) : 0.0f;
        tw1[tid] = v1 ? fy : 0.0f;
    }

    // zero halos of R / Rs (interior is fully overwritten later)
    if (tid < 28) {
        float* Rr = R + tid * 264;
        float* Rsr = Rs + tid * 264;
        Rr[0] = Rr[1] = Rr[2] = Rr[3] = 0.f;
        Rr[260] = Rr[261] = Rr[262] = Rr[263] = 0.f;
        Rsr[0] = Rsr[1] = Rsr[2] = 0.f;
        Rsr[259] = Rsr[260] = Rsr[261] = Rsr[262] = Rsr[263] = 0.f;
    }
    __syncthreads();

    const int wp = tid >> 5;
    const int lane = tid & 31;
    const int o0 = wp * 4;
    const float* xbase = x + (size_t)b * (CIN * HH * WW);

    // stage raw x rows for group g into xbuf[nb] via cp.async (skip dead taps)
    auto stage = [&](int g, int nb) {
        float* dst0 = xbf + nb * 14336;
#pragma unroll
        for (int k = 0; k < 16; k++) {
            int chunk = tid + 224 * k;     // 0..3583
            int row = chunk >> 6;          // 0..55  = (2i+t)*4 + c
            int off = (chunk & 63) << 2;   // float offset, 16B chunks
            int itap = row >> 2, c = row & 3;
            int i = itap >> 1;
            float a0 = tw0[g * 7 + i], a1 = tw1[g * 7 + i];
            if (a0 != 0.f || a1 != 0.f) {
                int y = ((itap & 1) ? y1c : y0c)[g * 7 + i];
                const float* src = xbase + ((size_t)(g * CPG + c) * HH + y) * WW + off;
                cp16(dst0 + row * 256 + off, src);
            }
        }
        asm volatile("cp.async.commit_group;" ::: "memory");
    };

    stage(0, 0);

    // ---- phase B: stage-1 contraction, accumulators are f32x2 pairs ----
    ull acc[4][4];
#pragma unroll
    for (int oo = 0; oo < 4; oo++) {
        ull bv = pk1(b1s[o0 + oo]);
#pragma unroll
        for (int p = 0; p < 4; p++) acc[oo][p] = bv;
    }

#pragma unroll 1
    for (int g = 0; g < 7; g++) {
        if (g < 6) {
            stage(g + 1, (g + 1) & 1);
            asm volatile("cp.async.wait_group 1;" ::: "memory");
        } else {
            asm volatile("cp.async.wait_group 0;" ::: "memory");
        }
        __syncthreads();
        const float* xb0 = xbf + (g & 1) * 14336;
#pragma unroll 1
        for (int i = 0; i < 7; i++) {
            float f0 = tw0[g * 7 + i], f1 = tw1[g * 7 + i];
            if (f0 == 0.f && f1 == 0.f) continue;   // uniform across CTA
            ull lw0 = pk1(f0), lw1 = pk1(f1);
#pragma unroll
            for (int c = 0; c < 4; c++) {
                const float* r0 = xb0 + (i * 8 + c) * 256;
                const float* r1 = xb0 + (i * 8 + 4 + c) * 256;
                const float* wb = W1s + ((g * 7 + i) * 4 + c) * 28 + o0;
                ull wv0 = pk1(wb[0]);
                ull wv1 = pk1(wb[1]);
                ull wv2 = pk1(wb[2]);
                ull wv3 = pk1(wb[3]);
#pragma unroll
                for (int p = 0; p < 4; p++) {
                    int q = 2 * lane + 64 * p;
                    ull xv0 = *(const ull*)(r0 + q);
                    ull xv1 = *(const ull*)(r1 + q);
                    ull s = f2fma(lw1, xv1, f2mul(lw0, xv0));
                    acc[0][p] = f2fma(wv0, s, acc[0][p]);
                    acc[1][p] = f2fma(wv1, s, acc[1][p]);
                    acc[2][p] = f2fma(wv2, s, acc[2][p]);
                    acc[3][p] = f2fma(wv3, s, acc[3][p]);
                }
            }
        }
        __syncthreads();
    }

    // write out1 row into R (offset +4) and shifted copy Rs (offset +3)
#pragma unroll
    for (int oo = 0; oo < 4; oo++) {
        float* Rr = R + (o0 + oo) * 264;
        float* Rsr = Rs + (o0 + oo) * 264;
#pragma unroll
        for (int p = 0; p < 4; p++) {
            int base = 2 * lane + 64 * p;
            *(ull*)(Rr + 4 + base) = acc[oo][p];
            float a0, a1; upk(acc[oo][p], a0, a1);
            Rsr[3 + base] = a0;
            Rsr[4 + base] = a1;
        }
    }
    __syncthreads();

    // ---- phase C: 1x7 conv along W with stage-3 folded weights ----
    ull acc2[4][4];
#pragma unroll
    for (int oo = 0; oo < 4; oo++) {
        ull bv = pk1(b2s[o0 + oo]);
#pragma unroll
        for (int p = 0; p < 4; p++) acc2[oo][p] = bv;
    }

#pragma unroll 1
    for (int o2 = 0; o2 < 28; o2++) {
        ull w2[4][7];
#pragma unroll
        for (int kw = 0; kw < 7; kw++) {
            const float* wb = W2s + (o2 * 7 + kw) * 28 + o0;
            w2[0][kw] = pk1(wb[0]);
            w2[1][kw] = pk1(wb[1]);
            w2[2][kw] = pk1(wb[2]);
            w2[3][kw] = pk1(wb[3]);
        }
        const float* Ro = R + o2 * 264;
        const float* Rso = Rs + o2 * 264;
#pragma unroll
        for (int p = 0; p < 4; p++) {
            int base = 2 * lane + 64 * p;
#pragma unroll
            for (int kw = 0; kw < 7; kw++) {
                // pair (out1[w+kw-3], out1[w+1+kw-3]); odd kw aligned in R, even kw in Rs
                ull v = (kw & 1) ? *(const ull*)(Ro + base + kw + 1)
                                 : *(const ull*)(Rso + base + kw);
                acc2[0][p] = f2fma(w2[0][kw], v, acc2[0][p]);
                acc2[1][p] = f2fma(w2[1][kw], v, acc2[1][p]);
                acc2[2][p] = f2fma(w2[2][kw], v, acc2[2][p]);
                acc2[3][p] = f2fma(w2[3][kw], v, acc2[3][p]);
            }
        }
    }

    // store final output (8B coalesced)
#pragma unroll
    for (int oo = 0; oo < 4; oo++) {
        size_t ob = (((size_t)b * COUT + o0 + oo) * HH + h) * WW;
#pragma unroll
        for (int p = 0; p < 4; p++) {
            int base = 2 * lane + 64 * p;
            *(ull*)(out + ob + base) = acc2[oo][p];
        }
    }
}

extern "C" void kernel_launch(void* const* d_in, const int* in_sizes, int n_in,
                              void* d_out, int out_size) {
    const float* x      = (const float*)d_in[0];
    const float* weight = (const float*)d_in[1];
    const float* bias   = (const float*)d_in[2];
    const float* w_t    = (const float*)d_in[3];
    const float* b_t    = (const float*)d_in[4];
    const float* w_m    = (const float*)d_in[5];
    const float* b_m    = (const float*)d_in[6];
    float* out = (float*)d_out;

    cudaFuncSetAttribute(harmonic_kernel, cudaFuncAttributeMaxDynamicSharedMemorySize,
                         SMEM_BYTES);

    prep_kernel<<<1, 256>>>(weight, w_t, b_t, w_m, b_m);
    harmonic_kernel<<<dim3(HH, BATCH), 224, SMEM_BYTES>>>(x, bias, out);
}

// round 2
// speedup vs baseline: 1.0838x; 1.0838x over previous
#include <cuda_runtime.h>
#include <cstdint>
#include <math.h>

#define BATCH 8
#define CIN   28
#define COUT  28
#define HH    256
#define WW    256
#define DGRP  7
#define KHT   7
#define CPG   4
#define HW    (HH*WW)

typedef unsigned long long ull;

// ---- packed f32x2 helpers ----
__device__ __forceinline__ ull pk2(float a, float b) {
    ull r; asm("mov.b64 %0, {%1,%2};" : "=l"(r) : "f"(a), "f"(b)); return r;
}
__device__ __forceinline__ ull pk1(float a) { return pk2(a, a); }
__device__ __forceinline__ ull f2fma(ull a, ull b, ull c) {
    ull d; asm("fma.rn.f32x2 %0, %1, %2, %3;" : "=l"(d) : "l"(a), "l"(b), "l"(c)); return d;
}
__device__ __forceinline__ ull f2mul(ull a, ull b) {
    ull d; asm("mul.rn.f32x2 %0, %1, %2;" : "=l"(d) : "l"(a), "l"(b)); return d;
}
__device__ __forceinline__ void cp16(void* dst, const void* src) {
    unsigned s = (unsigned)__cvta_generic_to_shared(dst);
    asm volatile("cp.async.cg.shared.global [%0], [%1], 16;" :: "r"(s), "l"(src));
}
__device__ __forceinline__ ull splat_dev(float v) {
    unsigned u = __float_as_uint(v); return ((ull)u << 32) | (ull)u;
}

// ---- global scratch ----
__device__ float g_mid[(size_t)BATCH * COUT * HH * WW];   // stage-1 output, 58.7MB (L2-resident)
__device__ ull   g_W1P[DGRP * KHT * CPG * COUT];          // splat pairs [tap][c][o]
__device__ ull   g_W2P[COUT * 7 * COUT];                  // splat pairs [o2][kw][oc], stage-3 folded
__device__ float g_b2[COUT];

__global__ void prep_kernel(const float* __restrict__ weight, const float* __restrict__ w_t,
                            const float* __restrict__ b_t, const float* __restrict__ w_m,
                            const float* __restrict__ b_m) {
    int t = threadIdx.x;
    for (int idx = t; idx < DGRP * KHT * CPG * COUT; idx += blockDim.x) {
        int o = idx % COUT;
        int c = (idx / COUT) % CPG;
        int i = (idx / (COUT * CPG)) % KHT;
        int g = idx / (COUT * CPG * KHT);
        g_W1P[idx] = splat_dev(weight[(o * CIN + (g * CPG + c)) * KHT + i]);
    }
    for (int idx = t; idx < COUT * 7 * COUT; idx += blockDim.x) {
        int oc = idx % COUT;
        int kw = (idx / COUT) % 7;
        int o2 = idx / (COUT * 7);
        int f = oc >> 2, cc = oc & 3;
        float s = 0.f;
#pragma unroll
        for (int g = 0; g < DGRP; g++)
            s += w_m[f * DGRP + g] * w_t[((g * CPG + cc) * COUT + o2) * 7 + kw];
        g_W2P[idx] = splat_dev(s);
    }
    if (t < COUT) {
        int f = t >> 2, cc = t & 3;
        float s = 0.f;
#pragma unroll
        for (int g = 0; g < DGRP; g++) s += w_m[f * DGRP + g] * b_t[g * CPG + cc];
        g_b2[t] = s + b_m[f];
    }
}

// =========================== Stage 1 =================================
// CTA = (h, b). 256 threads: p = tid&127 owns the w-pair (2p, 2p+1),
// oh = tid>>7 owns output channels [oh*14, oh*14+14).
// x pairs read straight from global (L2); weights via LDS.128 broadcast.

constexpr int A_W1  = 0;                      // ull[5488]
constexpr int A_B1  = 43904;                  // float[28] (pad 128)
constexpr int A_TL0 = A_B1 + 128;             // ull[49] pad 512
constexpr int A_TL1 = A_TL0 + 512;
constexpr int A_Y0  = A_TL1 + 512;            // int[49] pad 256
constexpr int A_Y1  = A_Y0 + 256;
constexpr int A_LT  = A_Y1 + 256;             // compacted: tap idx
constexpr int A_LG  = A_LT + 256;             // g
constexpr int A_LY0 = A_LG + 256;
constexpr int A_LY1 = A_LY0 + 256;
constexpr int A_LW0 = A_LY1 + 256;            // ull[49] pad 512
constexpr int A_LW1 = A_LW0 + 512;
constexpr int A_NL  = A_LW1 + 512;            // int
constexpr int A_SMEM = A_NL + 16;             // ~47.4KB

__global__ void __launch_bounds__(256, 3)
stage1_kernel(const float* __restrict__ x, const float* __restrict__ bias1) {
    extern __shared__ char sm[];
    ull*  W1p  = (ull*)(sm + A_W1);
    float* b1s = (float*)(sm + A_B1);
    ull*  tl0  = (ull*)(sm + A_TL0);
    ull*  tl1  = (ull*)(sm + A_TL1);
    int*  y0c  = (int*)(sm + A_Y0);
    int*  y1c  = (int*)(sm + A_Y1);
    int*  lTap = (int*)(sm + A_LT);
    int*  lG   = (int*)(sm + A_LG);
    int*  lY0  = (int*)(sm + A_LY0);
    int*  lY1  = (int*)(sm + A_LY1);
    ull*  lw0a = (ull*)(sm + A_LW0);
    ull*  lw1a = (ull*)(sm + A_LW1);
    int*  nLp  = (int*)(sm + A_NL);

    const int tid = threadIdx.x;
    const int h = blockIdx.x;
    const int b = blockIdx.y;

    for (int idx = tid; idx < 5488; idx += 256) W1p[idx] = g_W1P[idx];
    if (tid < 28) b1s[tid] = bias1[tid];

    if (tid < 49) {
        int g = tid / 7, i = tid % 7;
        double yp = (double)((h + 1) * (i + 1)) / (double)(g + 1) - 4.0;
        double y0 = floor(yp);
        float fy = (float)(yp - y0);
        int y0i = (int)y0;
        bool v0 = (y0i >= 0) && (y0i <= HH - 1);
        bool v1 = (y0i + 1 >= 0) && (y0i + 1 <= HH - 1);
        y0c[tid] = y0i < 0 ? 0 : (y0i > HH - 1 ? HH - 1 : y0i);
        y1c[tid] = (y0i + 1) < 0 ? 0 : (y0i + 1 > HH - 1 ? HH - 1 : y0i + 1);
        tl0[tid] = v0 ? pk1(1.0f - fy) : 0ull;
        tl1[tid] = v1 ? pk1(fy) : 0ull;
    }
    __syncthreads();
    if (tid == 0) {
        int n = 0;
        for (int t = 0; t < 49; t++) {
            if ((tl0[t] | tl1[t]) != 0ull) {
                lTap[n] = t; lG[n] = t / 7;
                lY0[n] = y0c[t]; lY1[n] = y1c[t];
                lw0a[n] = tl0[t]; lw1a[n] = tl1[t];
                n++;
            }
        }
        *nLp = n;
    }
    __syncthreads();

    const int p = tid & 127;
    const int oh = tid >> 7;
    const int wbase = 2 * p;

    ull acc[14];
#pragma unroll
    for (int o = 0; o < 14; o++) acc[o] = pk1(b1s[oh * 14 + o]);

    const float* xb = x + (size_t)b * CIN * HW + wbase;
    const int nl = *nLp;

#pragma unroll 1
    for (int t = 0; t < nl; t++) {
        const int tap = lTap[t];
        const int g = lG[t];
        const int y0 = lY0[t], y1 = lY1[t];
        const ull lw0 = lw0a[t], lw1 = lw1a[t];
        const float* rb = xb + (size_t)g * CPG * HW;
        ull s[4];
#pragma unroll
        for (int c = 0; c < 4; c++) {
            ull xv0 = *(const ull*)(rb + c * HW + y0 * WW);
            ull xv1 = *(const ull*)(rb + c * HW + y1 * WW);
            s[c] = f2fma(lw1, xv1, f2mul(lw0, xv0));
        }
#pragma unroll
        for (int c = 0; c < 4; c++) {
            const ulonglong2* wc = (const ulonglong2*)(W1p + (tap * 4 + c) * 28 + oh * 14);
#pragma unroll
            for (int oo = 0; oo < 7; oo++) {
                ulonglong2 w = wc[oo];
                acc[2 * oo]     = f2fma(w.x, s[c], acc[2 * oo]);
                acc[2 * oo + 1] = f2fma(w.y, s[c], acc[2 * oo + 1]);
            }
        }
    }

    float* mb = g_mid + (((size_t)b * COUT + oh * 14) * HH + h) * WW + wbase;
#pragma unroll
    for (int o = 0; o < 14; o++) *(ull*)(mb + (size_t)o * HW) = acc[o];
}

// =========================== Stage 2 (+3 folded) =====================
constexpr int B_W2  = 0;                        // ull[5488]
constexpr int B_B2  = 43904;                    // float[28] pad 128
constexpr int B_R   = B_B2 + 128;               // float[28*264]
constexpr int B_RS  = B_R + 28 * 264 * 4;       // float[28*264]
constexpr int B_SMEM = B_RS + 28 * 264 * 4;     // 103.2KB

__global__ void __launch_bounds__(256, 2)
stage2_kernel(float* __restrict__ out) {
    extern __shared__ char sm[];
    ull*   W2p = (ull*)(sm + B_W2);
    float* b2s = (float*)(sm + B_B2);
    float* R   = (float*)(sm + B_R);
    float* Rs  = (float*)(sm + B_RS);

    const int tid = threadIdx.x;
    const int h = blockIdx.x;
    const int b = blockIdx.y;

    // stage mid rows for this (b,h) into R (interior [4..259])
    const float* mrow = g_mid + ((size_t)b * COUT * HH + h) * WW;
#pragma unroll
    for (int k = 0; k < 7; k++) {
        int idx = tid + 256 * k;            // 0..1791
        int row = idx >> 6;                 // 0..27
        int ch  = idx & 63;                 // 16B chunk
        cp16(R + row * 264 + 4 + ch * 4, mrow + (size_t)row * HW + ch * 4);
    }
    asm volatile("cp.async.commit_group;" ::: "memory");

    for (int idx = tid; idx < 5488; idx += 256) W2p[idx] = g_W2P[idx];
    if (tid < 28) b2s[tid] = g_b2[tid];
    // halos
    if (tid < 28) {
        float* Rr = R + tid * 264;
        float* Rsr = Rs + tid * 264;
        Rr[0] = Rr[1] = Rr[2] = Rr[3] = 0.f;
        Rr[260] = Rr[261] = Rr[262] = Rr[263] = 0.f;
        Rsr[0] = Rsr[1] = Rsr[2] = 0.f;
        Rsr[259] = Rsr[260] = Rsr[261] = Rsr[262] = Rsr[263] = 0.f;
    }
    asm volatile("cp.async.wait_group 0;" ::: "memory");
    __syncthreads();

    // shifted copy: Rs[r][3+j] = R[r][4+j]
#pragma unroll
    for (int k = 0; k < 28; k++) {
        int idx = tid + 256 * k;            // 0..7167
        int r = idx >> 8, j = idx & 255;
        Rs[r * 264 + 3 + j] = R[r * 264 + 4 + j];
    }
    __syncthreads();

    const int p = tid & 127;
    const int oh = tid >> 7;
    const int base = 2 * p;

    ull acc[14];
#pragma unroll
    for (int o = 0; o < 14; o++) acc[o] = pk1(b2s[oh * 14 + o]);

#pragma unroll 1
    for (int o2 = 0; o2 < 28; o2++) {
        const float* Ro  = R + o2 * 264;
        const float* Rso = Rs + o2 * 264;
        const ull* wrow = W2p + o2 * 7 * 28 + oh * 14;
#pragma unroll
        for (int kw = 0; kw < 7; kw++) {
            ull v = (kw & 1) ? *(const ull*)(Ro + base + kw + 1)
                             : *(const ull*)(Rso + base + kw);
            const ulonglong2* wc = (const ulonglong2*)(wrow + kw * 28);
#pragma unroll
            for (int oo = 0; oo < 7; oo++) {
                ulonglong2 w = wc[oo];
                acc[2 * oo]     = f2fma(w.x, v, acc[2 * oo]);
                acc[2 * oo + 1] = f2fma(w.y, v, acc[2 * oo + 1]);
            }
        }
    }

    float* ob = out + (((size_t)b * COUT + oh * 14) * HH + h) * WW + base;
#pragma unroll
    for (int o = 0; o < 14; o++) *(ull*)(ob + (size_t)o * HW) = acc[o];
}

extern "C" void kernel_launch(void* const* d_in, const int* in_sizes, int n_in,
                              void* d_out, int out_size) {
    const float* x      = (const float*)d_in[0];
    const float* weight = (const float*)d_in[1];
    const float* bias   = (const float*)d_in[2];
    const float* w_t    = (const float*)d_in[3];
    const float* b_t    = (const float*)d_in[4];
    const float* w_m    = (const float*)d_in[5];
    const float* b_m    = (const float*)d_in[6];
    float* out = (float*)d_out;

    cudaFuncSetAttribute(stage1_kernel, cudaFuncAttributeMaxDynamicSharedMemorySize, A_SMEM);
    cudaFuncSetAttribute(stage2_kernel, cudaFuncAttributeMaxDynamicSharedMemorySize, B_SMEM);

    prep_kernel<<<1, 256>>>(weight, w_t, b_t, w_m, b_m);
    stage1_kernel<<<dim3(HH, BATCH), 256, A_SMEM>>>(x, bias);
    stage2_kernel<<<dim3(HH, BATCH), 256, B_SMEM>>>(out);
}

// round 3
// speedup vs baseline: 1.4298x; 1.3192x over previous
#include <cuda_runtime.h>
#include <cstdint>
#include <math.h>

#define BATCH 8
#define CIN   28
#define COUT  28
#define HH    256
#define WW    256
#define DGRP  7
#define KHT   7
#define CPG   4
#define HW    (HH*WW)

typedef unsigned long long ull;

__device__ __forceinline__ ull pk2(float a, float b) {
    ull r; asm("mov.b64 %0, {%1,%2};" : "=l"(r) : "f"(a), "f"(b)); return r;
}
__device__ __forceinline__ ull pk1(float a) { return pk2(a, a); }
__device__ __forceinline__ ull f2fma(ull a, ull b, ull c) {
    ull d; asm("fma.rn.f32x2 %0, %1, %2, %3;" : "=l"(d) : "l"(a), "l"(b), "l"(c)); return d;
}
__device__ __forceinline__ ull f2mul(ull a, ull b) {
    ull d; asm("mul.rn.f32x2 %0, %1, %2;" : "=l"(d) : "l"(a), "l"(b)); return d;
}
__device__ __forceinline__ void cp16(void* dst, const void* src) {
    unsigned s = (unsigned)__cvta_generic_to_shared(dst);
    asm volatile("cp.async.cg.shared.global [%0], [%1], 16;" :: "r"(s), "l"(src));
}
__device__ __forceinline__ ull splat_dev(float v) {
    unsigned u = __float_as_uint(v); return ((ull)u << 32) | (ull)u;
}

// ---- global scratch ----
__device__ float g_mid[(size_t)BATCH * COUT * HH * WW];   // 58.7MB stage-1 output
__device__ ull   g_W1P[2 * DGRP * KHT * CPG * 2 * 7];     // [tap][c][ohh][j] -> ull2 pair
__device__ ull   g_W2P[2 * COUT * 7 * 4 * 4];             // [o2][kw][ohq][j] -> ull2 pair (ch pad)
__device__ float g_b2[COUT];

__global__ void prep_kernel(const float* __restrict__ weight, const float* __restrict__ w_t,
                            const float* __restrict__ b_t, const float* __restrict__ w_m,
                            const float* __restrict__ b_m) {
    int gid = blockIdx.x * blockDim.x + threadIdx.x;
    int nth = gridDim.x * blockDim.x;

    // W1P: entries e in [0, 2744): e = ((tap*4+c)*2+ohh)*7+j ; channels 2j,2j+1 of half ohh
    for (int e = gid; e < 2744; e += nth) {
        int j = e % 7; int r = e / 7;
        int ohh = r & 1; r >>= 1;
        int c = r & 3; int tap = r >> 2;
        int g = tap / 7, i = tap % 7;
        int o0 = ohh * 14 + 2 * j;
        float wa = weight[(o0 * CIN + (g * CPG + c)) * KHT + i];
        float wb = weight[((o0 + 1) * CIN + (g * CPG + c)) * KHT + i];
        g_W1P[2 * e]     = splat_dev(wa);
        g_W1P[2 * e + 1] = splat_dev(wb);
    }

    // W2P: entries e2 in [0, 3136): e2 = ((o2*7+kw)*4+ohq)*4+j ; channels ohq*7+2j, +2j+1
    for (int e2 = gid; e2 < 3136; e2 += nth) {
        int j = e2 & 3; int q = e2 >> 2;
        int ohq = q & 3; q >>= 2;
        int kw = q % 7; int o2 = q / 7;
        float va = 0.f, vb = 0.f;
        int oc0 = ohq * 7 + 2 * j;
        {
            int f = oc0 >> 2, cc = oc0 & 3;
#pragma unroll
            for (int g = 0; g < DGRP; g++)
                va += w_m[f * DGRP + g] * w_t[((g * CPG + cc) * COUT + o2) * 7 + kw];
        }
        if (2 * j + 1 < 7) {
            int oc1 = oc0 + 1;
            int f = oc1 >> 2, cc = oc1 & 3;
#pragma unroll
            for (int g = 0; g < DGRP; g++)
                vb += w_m[f * DGRP + g] * w_t[((g * CPG + cc) * COUT + o2) * 7 + kw];
        }
        g_W2P[2 * e2]     = splat_dev(va);
        g_W2P[2 * e2 + 1] = splat_dev(vb);
    }

    if (gid < COUT) {
        int f = gid >> 2, cc = gid & 3;
        float s = 0.f;
#pragma unroll
        for (int g = 0; g < DGRP; g++) s += w_m[f * DGRP + g] * b_t[g * CPG + cc];
        g_b2[gid] = s + b_m[f];
    }
}

// =========================== Stage 1 =================================
// CTA = 256 threads, covers 2 h-rows. Per half: p=t&63 owns float4 at w=4p,
// ohh=t>>6 owns 14 channels. x via LDG.128 from global (L2-hot).

constexpr int A_W1   = 0;                        // ull[5488] 43904
constexpr int A_B1   = 43904;                    // float[32]
constexpr int A_MT   = 44032;                    // int[128] tap
constexpr int A_MG   = A_MT + 512;               // int[128] g
constexpr int A_MY0  = A_MG + 512;
constexpr int A_MY1  = A_MY0 + 512;
constexpr int A_MW0  = A_MY1 + 512;              // ull[128]
constexpr int A_MW1  = A_MW0 + 1024;
constexpr int A_MNL  = A_MW1 + 1024;             // int[4]
constexpr int A_TL0  = A_MNL + 16;               // ull[128]
constexpr int A_TL1  = A_TL0 + 1024;
constexpr int A_TY0  = A_TL1 + 1024;             // int[128]
constexpr int A_TY1  = A_TY0 + 512;
constexpr int A_SMEM = A_TY1 + 512;              // ~51.7KB

__global__ void __launch_bounds__(256, 2)
stage1_kernel(const float* __restrict__ x, const float* __restrict__ bias1) {
    extern __shared__ char sm[];
    ull*   W1p  = (ull*)(sm + A_W1);
    float* b1s  = (float*)(sm + A_B1);
    int*   mTap = (int*)(sm + A_MT);
    int*   mG   = (int*)(sm + A_MG);
    int*   mY0  = (int*)(sm + A_MY0);
    int*   mY1  = (int*)(sm + A_MY1);
    ull*   mW0  = (ull*)(sm + A_MW0);
    ull*   mW1  = (ull*)(sm + A_MW1);
    int*   mNL  = (int*)(sm + A_MNL);
    ull*   tl0  = (ull*)(sm + A_TL0);
    ull*   tl1  = (ull*)(sm + A_TL1);
    int*   ty0  = (int*)(sm + A_TY0);
    int*   ty1  = (int*)(sm + A_TY1);

    const int tid = threadIdx.x;
    const int hz  = tid >> 7;
    const int t   = tid & 127;
    const int h   = blockIdx.x * 2 + hz;
    const int b   = blockIdx.y;

    for (int i = tid; i < 5488; i += 256) W1p[i] = g_W1P[i];
    if (tid < 28) b1s[tid] = bias1[tid];

    if (t < 49) {
        int g = t / 7, i = t % 7;
        double yp = (double)((h + 1) * (i + 1)) / (double)(g + 1) - 4.0;
        double y0 = floor(yp);
        float fy = (float)(yp - y0);
        int y0i = (int)y0;
        bool v0 = (y0i >= 0) && (y0i <= HH - 1);
        bool v1 = (y0i + 1 >= 0) && (y0i + 1 <= HH - 1);
        ty0[hz * 64 + t] = y0i < 0 ? 0 : (y0i > HH - 1 ? HH - 1 : y0i);
        ty1[hz * 64 + t] = (y0i + 1) < 0 ? 0 : (y0i + 1 > HH - 1 ? HH - 1 : y0i + 1);
        tl0[hz * 64 + t] = v0 ? pk1(1.0f - fy) : 0ull;
        tl1[hz * 64 + t] = v1 ? pk1(fy) : 0ull;
    }
    __syncthreads();
    if (t == 0) {
        int n = 0;
        for (int k = 0; k < 49; k++) {
            if ((tl0[hz * 64 + k] | tl1[hz * 64 + k]) != 0ull) {
                mTap[hz * 64 + n] = k;
                mG[hz * 64 + n]   = k / 7;
                mY0[hz * 64 + n]  = ty0[hz * 64 + k];
                mY1[hz * 64 + n]  = ty1[hz * 64 + k];
                mW0[hz * 64 + n]  = tl0[hz * 64 + k];
                mW1[hz * 64 + n]  = tl1[hz * 64 + k];
                n++;
            }
        }
        mNL[hz] = n;
    }
    __syncthreads();

    const int p = t & 63;
    const int ohh = t >> 6;
    const int wbase = 4 * p;

    ull acc[14][2];
#pragma unroll
    for (int o = 0; o < 14; o++) { ull bv = pk1(b1s[ohh * 14 + o]); acc[o][0] = bv; acc[o][1] = bv; }

    const float* xb = x + (size_t)b * CIN * HW + wbase;
    const int nl = mNL[hz];
    const int mbase = hz * 64;

#pragma unroll 1
    for (int tt = 0; tt < nl; tt++) {
        const int tap = mTap[mbase + tt];
        const int g   = mG[mbase + tt];
        const int y0  = mY0[mbase + tt];
        const int y1  = mY1[mbase + tt];
        const ull lw0 = mW0[mbase + tt];
        const ull lw1 = mW1[mbase + tt];
        const float* rb = xb + (size_t)g * CPG * HW;
        ull s[4][2];
#pragma unroll
        for (int c = 0; c < 4; c++) {
            const ulonglong2 xv0 = *(const ulonglong2*)(rb + (size_t)c * HW + y0 * WW);
            const ulonglong2 xv1 = *(const ulonglong2*)(rb + (size_t)c * HW + y1 * WW);
            s[c][0] = f2fma(lw1, xv1.x, f2mul(lw0, xv0.x));
            s[c][1] = f2fma(lw1, xv1.y, f2mul(lw0, xv0.y));
        }
#pragma unroll
        for (int c = 0; c < 4; c++) {
            const ulonglong2* wc = (const ulonglong2*)W1p + ((tap * 4 + c) * 2 + ohh) * 7;
#pragma unroll
            for (int j = 0; j < 7; j++) {
                ulonglong2 w = wc[j];
                acc[2 * j][0]     = f2fma(w.x, s[c][0], acc[2 * j][0]);
                acc[2 * j][1]     = f2fma(w.x, s[c][1], acc[2 * j][1]);
                acc[2 * j + 1][0] = f2fma(w.y, s[c][0], acc[2 * j + 1][0]);
                acc[2 * j + 1][1] = f2fma(w.y, s[c][1], acc[2 * j + 1][1]);
            }
        }
    }

    float* mb = g_mid + (((size_t)b * COUT + ohh * 14) * HH + h) * WW + wbase;
#pragma unroll
    for (int o = 0; o < 14; o++) {
        ulonglong2 v; v.x = acc[o][0]; v.y = acc[o][1];
        *(ulonglong2*)(mb + (size_t)o * HW) = v;
    }
}

// =========================== Stage 2 (+3 folded) =====================
constexpr int B_W2   = 0;                        // ull[6272] 50176
constexpr int B_B2   = 50176;                    // float[32]
constexpr int B_R    = 50304;                    // float[28*264] 29568
constexpr int B_SMEM = B_R + 29568;              // 79872

__global__ void __launch_bounds__(256, 2)
stage2_kernel(float* __restrict__ out) {
    extern __shared__ char sm[];
    ull*   W2p = (ull*)(sm + B_W2);
    float* b2s = (float*)(sm + B_B2);
    float* R   = (float*)(sm + B_R);

    const int tid = threadIdx.x;
    const int h = blockIdx.x;
    const int b = blockIdx.y;

    const float* mrow = g_mid + ((size_t)b * COUT * HH + h) * WW;
#pragma unroll
    for (int k = 0; k < 7; k++) {
        int idx = tid + 256 * k;
        int row = idx >> 6;
        int ch  = idx & 63;
        cp16(R + row * 264 + 4 + ch * 4, mrow + (size_t)row * HW + ch * 4);
    }
    asm volatile("cp.async.commit_group;" ::: "memory");

    for (int i = tid; i < 6272; i += 256) W2p[i] = g_W2P[i];
    if (tid < 28) b2s[tid] = g_b2[tid];
    if (tid < 28) {
        float* Rr = R + tid * 264;
        Rr[0] = Rr[1] = Rr[2] = Rr[3] = 0.f;
        Rr[260] = Rr[261] = Rr[262] = Rr[263] = 0.f;
    }
    asm volatile("cp.async.wait_group 0;" ::: "memory");
    __syncthreads();

    const int p = tid & 63;
    const int ohq = tid >> 6;
    const int base = 4 * p;

    ull acc[7][2];
#pragma unroll
    for (int o = 0; o < 7; o++) { ull bv = pk1(b2s[ohq * 7 + o]); acc[o][0] = bv; acc[o][1] = bv; }

#pragma unroll 1
    for (int o2 = 0; o2 < 28; o2++) {
        const float4* Rw = (const float4*)(R + o2 * 264 + base);
        float r[12];
        *(float4*)(r)     = Rw[0];
        *(float4*)(r + 4) = Rw[1];
        *(float4*)(r + 8) = Rw[2];
#pragma unroll
        for (int kw = 0; kw < 7; kw++) {
            ull vA = pk2(r[kw + 1], r[kw + 2]);
            ull vB = pk2(r[kw + 3], r[kw + 4]);
            const ulonglong2* wq = (const ulonglong2*)W2p + (((o2 * 7 + kw) * 4 + ohq) << 2);
            ulonglong2 w0 = wq[0], w1 = wq[1], w2 = wq[2], w3 = wq[3];
            acc[0][0] = f2fma(w0.x, vA, acc[0][0]); acc[0][1] = f2fma(w0.x, vB, acc[0][1]);
            acc[1][0] = f2fma(w0.y, vA, acc[1][0]); acc[1][1] = f2fma(w0.y, vB, acc[1][1]);
            acc[2][0] = f2fma(w1.x, vA, acc[2][0]); acc[2][1] = f2fma(w1.x, vB, acc[2][1]);
            acc[3][0] = f2fma(w1.y, vA, acc[3][0]); acc[3][1] = f2fma(w1.y, vB, acc[3][1]);
            acc[4][0] = f2fma(w2.x, vA, acc[4][0]); acc[4][1] = f2fma(w2.x, vB, acc[4][1]);
            acc[5][0] = f2fma(w2.y, vA, acc[5][0]); acc[5][1] = f2fma(w2.y, vB, acc[5][1]);
            acc[6][0] = f2fma(w3.x, vA, acc[6][0]); acc[6][1] = f2fma(w3.x, vB, acc[6][1]);
        }
    }

    float* ob = out + (((size_t)b * COUT + ohq * 7) * HH + h) * WW + base;
#pragma unroll
    for (int o = 0; o < 7; o++) {
        ulonglong2 v; v.x = acc[o][0]; v.y = acc[o][1];
        *(ulonglong2*)(ob + (size_t)o * HW) = v;
    }
}

extern "C" void kernel_launch(void* const* d_in, const int* in_sizes, int n_in,
                              void* d_out, int out_size) {
    const float* x      = (const float*)d_in[0];
    const float* weight = (const float*)d_in[1];
    const float* bias   = (const float*)d_in[2];
    const float* w_t    = (const float*)d_in[3];
    const float* b_t    = (const float*)d_in[4];
    const float* w_m    = (const float*)d_in[5];
    const float* b_m    = (const float*)d_in[6];
    float* out = (float*)d_out;

    cudaFuncSetAttribute(stage1_kernel, cudaFuncAttributeMaxDynamicSharedMemorySize, A_SMEM);
    cudaFuncSetAttribute(stage2_kernel, cudaFuncAttributeMaxDynamicSharedMemorySize, B_SMEM);

    prep_kernel<<<32, 256>>>(weight, w_t, b_t, w_m, b_m);
    stage1_kernel<<<dim3(HH / 2, BATCH), 256, A_SMEM>>>(x, bias);
    stage2_kernel<<<dim3(HH, BATCH), 256, B_SMEM>>>(out);
}